// round 6
// baseline (speedup 1.0000x reference)
#include <cuda_runtime.h>

#define NT 100000
#define NC 100000
#define NE 1600000
#define NP 200000
#define HD 128

// ---- scratch (static __device__, zero at load; k_u restores zeros each call) ----
__device__ float  g_dis_t[NT];     // truck deg -> dis_t
__device__ float  g_sum_t[NT];     // unscaled truck sum
__device__ float  g_deg_c[NC];     // car weighted degree
__device__ float4 g_gc4[NC];       // unscaled car sum
__device__ float4 g_xd4[NC];       // packed (x0,x1,x2,dis_c)
__device__ float4 g_u[NT + NC];    // per-node compact coefficients
__device__ float  g_M[36];         // 6x6 quadratic-form matrix

__device__ __forceinline__ void red_add_v4(float4* addr, float a, float b, float c, float d) {
    asm volatile("red.global.add.v4.f32 [%0], {%1,%2,%3,%4};"
                 :: "l"(addr), "f"(a), "f"(b), "f"(c), "f"(d) : "memory");
}

// ---- kM: 6x6 quadratic form ----
__global__ void k_M(const float* __restrict__ Wt, const float* __restrict__ bt,
                    const float* __restrict__ Wc, const float* __restrict__ bc,
                    const float* __restrict__ wl) {
    __shared__ float B[6][HD];
    __shared__ float Bw[HD];
    int h = threadIdx.x;  // 128 threads
    B[0][h] = Wt[h];
    B[1][h] = bt[h];
    B[2][h] = Wc[h];
    B[3][h] = Wc[HD + h];
    B[4][h] = Wc[2 * HD + h];
    B[5][h] = bc[h];
    Bw[h] = wl[h];
    __syncthreads();
    int warp = h >> 5, lane = h & 31;
    for (int pi = warp; pi < 36; pi += 4) {
        int i = pi / 6, j = pi % 6;
        float s = 0.f;
        #pragma unroll
        for (int t = lane; t < HD; t += 32)
            s += B[i][t] * B[j][t] * Bw[t];
        #pragma unroll
        for (int o = 16; o > 0; o >>= 1)
            s += __shfl_xor_sync(0xffffffff, s, o);
        if (lane == 0) g_M[pi] = s;
    }
}

// ---- k1: degree accumulation, 8 edges/thread ----
__global__ void __launch_bounds__(256) k_deg(const int* __restrict__ eit,
                                             const int* __restrict__ eic,
                                             const float* __restrict__ ew) {
    int t = blockIdx.x * blockDim.x + threadIdx.x;
    int base = t * 8;
    if (base >= NE) return;
    int4   ct4a = *(const int4*)(eit + NE + base);
    int4   ct4b = *(const int4*)(eit + NE + base + 4);
    int4   cc4a = *(const int4*)(eic + NE + base);
    int4   cc4b = *(const int4*)(eic + NE + base + 4);
    float4 w4a  = *(const float4*)(ew + base);
    float4 w4b  = *(const float4*)(ew + base + 4);
    int ct[8] = {ct4a.x, ct4a.y, ct4a.z, ct4a.w, ct4b.x, ct4b.y, ct4b.z, ct4b.w};
    int cc[8] = {cc4a.x, cc4a.y, cc4a.z, cc4a.w, cc4b.x, cc4b.y, cc4b.z, cc4b.w};
    float w[8] = {w4a.x, w4a.y, w4a.z, w4a.w, w4b.x, w4b.y, w4b.z, w4b.w};
    #pragma unroll
    for (int k = 0; k < 8; k++) atomicAdd(&g_dis_t[ct[k]], 1.0f);
    #pragma unroll
    for (int k = 0; k < 8; k++) atomicAdd(&g_deg_c[cc[k]], w[k]);
}

// ---- k2: deg -> dis; pack (x0,x1,x2,dis_c); 4 nodes/thread, vector loads ----
__global__ void __launch_bounds__(256) k_dis(const float* __restrict__ xcar) {
    int t = blockIdx.x * blockDim.x + threadIdx.x;
    int i = t * 4;
    if (i >= NC) return;
    float4 dt = *(float4*)&g_dis_t[i];
    float4 dc = *(float4*)&g_deg_c[i];
    float4 x0 = *(const float4*)(xcar + 3 * i);      // x[i].0,1,2  x[i+1].0
    float4 x1 = *(const float4*)(xcar + 3 * i + 4);  // x[i+1].1,2  x[i+2].0,1
    float4 x2 = *(const float4*)(xcar + 3 * i + 8);  // x[i+2].2    x[i+3].0,1,2
    dt.x = rsqrtf(dt.x + 1.0f); dt.y = rsqrtf(dt.y + 1.0f);
    dt.z = rsqrtf(dt.z + 1.0f); dt.w = rsqrtf(dt.w + 1.0f);
    *(float4*)&g_dis_t[i] = dt;
    float d0 = rsqrtf(dc.x + 1.0f), d1 = rsqrtf(dc.y + 1.0f);
    float d2 = rsqrtf(dc.z + 1.0f), d3 = rsqrtf(dc.w + 1.0f);
    g_xd4[i + 0] = make_float4(x0.x, x0.y, x0.z, d0);
    g_xd4[i + 1] = make_float4(x0.w, x1.x, x1.y, d1);
    g_xd4[i + 2] = make_float4(x1.z, x1.w, x2.x, d2);
    g_xd4[i + 3] = make_float4(x2.y, x2.z, x2.w, d3);
}

// ---- k3: edge aggregation, 8 edges/thread, unscaled sums ----
__global__ void __launch_bounds__(256) k_agg(const int* __restrict__ eit,
                                             const int* __restrict__ eic,
                                             const float* __restrict__ ew) {
    int t = blockIdx.x * blockDim.x + threadIdx.x;
    int base = t * 8;
    if (base >= NE) return;
    int4   rt4a = *(const int4*)(eit + base);
    int4   rt4b = *(const int4*)(eit + base + 4);
    int4   ct4a = *(const int4*)(eit + NE + base);
    int4   ct4b = *(const int4*)(eit + NE + base + 4);
    int4   rc4a = *(const int4*)(eic + base);
    int4   rc4b = *(const int4*)(eic + base + 4);
    int4   cc4a = *(const int4*)(eic + NE + base);
    int4   cc4b = *(const int4*)(eic + NE + base + 4);
    float4 w4a  = *(const float4*)(ew + base);
    float4 w4b  = *(const float4*)(ew + base + 4);

    int rt[8] = {rt4a.x, rt4a.y, rt4a.z, rt4a.w, rt4b.x, rt4b.y, rt4b.z, rt4b.w};
    int ct[8] = {ct4a.x, ct4a.y, ct4a.z, ct4a.w, ct4b.x, ct4b.y, ct4b.z, ct4b.w};
    int rc[8] = {rc4a.x, rc4a.y, rc4a.z, rc4a.w, rc4b.x, rc4b.y, rc4b.z, rc4b.w};
    int cc[8] = {cc4a.x, cc4a.y, cc4a.z, cc4a.w, cc4b.x, cc4b.y, cc4b.z, cc4b.w};
    float w[8] = {w4a.x, w4a.y, w4a.z, w4a.w, w4b.x, w4b.y, w4b.z, w4b.w};

    float dtr[8];
    float4 xd[8];
    #pragma unroll
    for (int k = 0; k < 8; k++) {
        dtr[k] = g_dis_t[rt[k]];
        xd[k]  = g_xd4[rc[k]];
    }
    #pragma unroll
    for (int k = 0; k < 8; k++) {
        atomicAdd(&g_sum_t[ct[k]], dtr[k]);
        float nw = xd[k].w * w[k];
        red_add_v4(&g_gc4[cc[k]], nw * xd[k].x, nw * xd[k].y, nw * xd[k].z, 0.f);
    }
}

// ---- k4: dest-side scaling + self-loops -> u; restore zeros for next call ----
__global__ void k_u() {
    int n = blockIdx.x * blockDim.x + threadIdx.x;
    if (n >= NT + NC) return;
    float4 u;
    if (n < NT) {
        float d = g_dis_t[n];
        u = make_float4(d * g_sum_t[n] + d * d, 1.f, 0.f, 0.f);
        g_dis_t[n] = 0.f;
        g_sum_t[n] = 0.f;
    } else {
        int c = n - NT;
        float4 gc = g_gc4[c];
        float4 xd = g_xd4[c];
        float d  = xd.w;
        float dd = d * d;
        u = make_float4(d * gc.x + dd * xd.x,
                        d * gc.y + dd * xd.y,
                        d * gc.z + dd * xd.z,
                        1.f);
        g_gc4[c] = make_float4(0.f, 0.f, 0.f, 0.f);
        g_deg_c[c] = 0.f;
    }
    g_u[n] = u;
}

// ---- k5: pair scoring, 2 pairs/thread ----
__global__ void __launch_bounds__(256) k_pair(const int* __restrict__ src,
                                              const int* __restrict__ dst,
                                              const float* __restrict__ bl,
                                              float* __restrict__ out) {
    __shared__ float M[36];
    if (threadIdx.x < 36) M[threadIdx.x] = g_M[threadIdx.x];
    __syncthreads();
    int t = blockIdx.x * blockDim.x + threadIdx.x;
    int base = t * 2;
    if (base >= NP) return;
    int2 s2 = *(const int2*)(src + base);
    int2 d2 = *(const int2*)(dst + base);
    float blv = bl[0];
    int ss[2] = {s2.x, s2.y};
    int dd[2] = {d2.x, d2.y};
    float4 usv[2], udv[2];
    #pragma unroll
    for (int k = 0; k < 2; k++) { usv[k] = g_u[ss[k]]; udv[k] = g_u[dd[k]]; }
    float res[2];
    #pragma unroll
    for (int k = 0; k < 2; k++) {
        float us[6] = {0.f, 0.f, 0.f, 0.f, 0.f, 0.f};
        float ud[6] = {0.f, 0.f, 0.f, 0.f, 0.f, 0.f};
        if (ss[k] < NT) { us[0] = usv[k].x; us[1] = usv[k].y; }
        else            { us[2] = usv[k].x; us[3] = usv[k].y; us[4] = usv[k].z; us[5] = usv[k].w; }
        if (dd[k] < NT) { ud[0] = udv[k].x; ud[1] = udv[k].y; }
        else            { ud[2] = udv[k].x; ud[3] = udv[k].y; ud[4] = udv[k].z; ud[5] = udv[k].w; }
        float acc = blv;
        #pragma unroll
        for (int i = 0; i < 6; i++) {
            float tt = 0.f;
            #pragma unroll
            for (int j = 0; j < 6; j++)
                tt += M[6 * i + j] * ud[j];
            acc += us[i] * tt;
        }
        res[k] = acc;
    }
    out[base] = res[0];
    if (base + 1 < NP) out[base + 1] = res[1];
}

extern "C" void kernel_launch(void* const* d_in, const int* in_sizes, int n_in,
                              void* d_out, int out_size) {
    const float* xcar = (const float*)d_in[0];
    const int*   eit  = (const int*)d_in[1];
    const int*   eic  = (const int*)d_in[2];
    const float* ew   = (const float*)d_in[3];
    const int*   src  = (const int*)d_in[4];
    const int*   dst  = (const int*)d_in[5];
    int w0 = (in_sizes[6] == 1) ? 7 : 6;
    const float* Wt = (const float*)d_in[w0 + 0];
    const float* bt = (const float*)d_in[w0 + 1];
    const float* Wc = (const float*)d_in[w0 + 2];
    const float* bc = (const float*)d_in[w0 + 3];
    const float* wl = (const float*)d_in[w0 + 4];
    const float* bl = (const float*)d_in[w0 + 5];
    float* out = (float*)d_out;

    const int TPB = 256;
    k_M<<<1, HD>>>(Wt, bt, Wc, bc, wl);
    k_deg<<<(NE / 8 + TPB - 1) / TPB, TPB>>>(eit, eic, ew);
    k_dis<<<(NC / 4 + TPB - 1) / TPB, TPB>>>(xcar);
    k_agg<<<(NE / 8 + TPB - 1) / TPB, TPB>>>(eit, eic, ew);
    k_u<<<(NT + NC + TPB - 1) / TPB, TPB>>>();
    k_pair<<<(NP / 2 + TPB - 1) / TPB, TPB>>>(src, dst, bl, out);
}

// round 7
// speedup vs baseline: 1.0433x; 1.0433x over previous
#include <cuda_runtime.h>

#define NT 100000
#define NC 100000
#define NE 1600000
#define NP 200000
#define HD 128

// ---- scratch (static __device__, zero at load; k_u restores zeros each call) ----
__device__ float  g_dis_t[NT];     // truck deg -> dis_t
__device__ float  g_sum_t[NT];     // unscaled truck sum
__device__ float  g_deg_c[NC];     // car weighted degree
__device__ float4 g_gc4[NC];       // unscaled car sum
__device__ float4 g_xd4[NC];       // packed (x0,x1,x2,dis_c)
__device__ float4 g_u[NT + NC];    // per-node compact coefficients
__device__ float  g_M[36];         // 6x6 quadratic-form matrix

__device__ __forceinline__ void red_add_v4(float4* addr, float a, float b, float c, float d) {
    asm volatile("red.global.add.v4.f32 [%0], {%1,%2,%3,%4};"
                 :: "l"(addr), "f"(a), "f"(b), "f"(c), "f"(d) : "memory");
}

// ---- kM: 6x6 quadratic form ----
__global__ void k_M(const float* __restrict__ Wt, const float* __restrict__ bt,
                    const float* __restrict__ Wc, const float* __restrict__ bc,
                    const float* __restrict__ wl) {
    __shared__ float B[6][HD];
    __shared__ float Bw[HD];
    int h = threadIdx.x;  // 128 threads
    B[0][h] = Wt[h];
    B[1][h] = bt[h];
    B[2][h] = Wc[h];
    B[3][h] = Wc[HD + h];
    B[4][h] = Wc[2 * HD + h];
    B[5][h] = bc[h];
    Bw[h] = wl[h];
    __syncthreads();
    int warp = h >> 5, lane = h & 31;
    for (int pi = warp; pi < 36; pi += 4) {
        int i = pi / 6, j = pi % 6;
        float s = 0.f;
        #pragma unroll
        for (int t = lane; t < HD; t += 32)
            s += B[i][t] * B[j][t] * Bw[t];
        #pragma unroll
        for (int o = 16; o > 0; o >>= 1)
            s += __shfl_xor_sync(0xffffffff, s, o);
        if (lane == 0) g_M[pi] = s;
    }
}

// ---- k1: degree accumulation, 4 edges/thread ----
__global__ void __launch_bounds__(256, 8) k_deg(const int* __restrict__ eit,
                                                const int* __restrict__ eic,
                                                const float* __restrict__ ew) {
    int t = blockIdx.x * blockDim.x + threadIdx.x;
    int base = t * 4;
    if (base >= NE) return;
    int4   ct4 = *(const int4*)(eit + NE + base);
    int4   cc4 = *(const int4*)(eic + NE + base);
    float4 w4  = *(const float4*)(ew + base);
    atomicAdd(&g_dis_t[ct4.x], 1.0f);
    atomicAdd(&g_dis_t[ct4.y], 1.0f);
    atomicAdd(&g_dis_t[ct4.z], 1.0f);
    atomicAdd(&g_dis_t[ct4.w], 1.0f);
    atomicAdd(&g_deg_c[cc4.x], w4.x);
    atomicAdd(&g_deg_c[cc4.y], w4.y);
    atomicAdd(&g_deg_c[cc4.z], w4.z);
    atomicAdd(&g_deg_c[cc4.w], w4.w);
}

// ---- k2: deg -> dis; pack (x0,x1,x2,dis_c); 4 nodes/thread, vector loads ----
__global__ void __launch_bounds__(256) k_dis(const float* __restrict__ xcar) {
    int t = blockIdx.x * blockDim.x + threadIdx.x;
    int i = t * 4;
    if (i >= NC) return;
    float4 dt = *(float4*)&g_dis_t[i];
    float4 dc = *(float4*)&g_deg_c[i];
    float4 x0 = *(const float4*)(xcar + 3 * i);
    float4 x1 = *(const float4*)(xcar + 3 * i + 4);
    float4 x2 = *(const float4*)(xcar + 3 * i + 8);
    dt.x = rsqrtf(dt.x + 1.0f); dt.y = rsqrtf(dt.y + 1.0f);
    dt.z = rsqrtf(dt.z + 1.0f); dt.w = rsqrtf(dt.w + 1.0f);
    *(float4*)&g_dis_t[i] = dt;
    float d0 = rsqrtf(dc.x + 1.0f), d1 = rsqrtf(dc.y + 1.0f);
    float d2 = rsqrtf(dc.z + 1.0f), d3 = rsqrtf(dc.w + 1.0f);
    g_xd4[i + 0] = make_float4(x0.x, x0.y, x0.z, d0);
    g_xd4[i + 1] = make_float4(x0.w, x1.x, x1.y, d1);
    g_xd4[i + 2] = make_float4(x1.z, x1.w, x2.x, d2);
    g_xd4[i + 3] = make_float4(x2.y, x2.z, x2.w, d3);
}

// ---- k3: edge aggregation, 4 edges/thread, unscaled sums ----
__global__ void __launch_bounds__(256, 6) k_agg(const int* __restrict__ eit,
                                                const int* __restrict__ eic,
                                                const float* __restrict__ ew) {
    int t = blockIdx.x * blockDim.x + threadIdx.x;
    int base = t * 4;
    if (base >= NE) return;
    int4   rt4 = *(const int4*)(eit + base);
    int4   ct4 = *(const int4*)(eit + NE + base);
    int4   rc4 = *(const int4*)(eic + base);
    int4   cc4 = *(const int4*)(eic + NE + base);
    float4 w4  = *(const float4*)(ew + base);

    int rt[4] = {rt4.x, rt4.y, rt4.z, rt4.w};
    int ct[4] = {ct4.x, ct4.y, ct4.z, ct4.w};
    int rc[4] = {rc4.x, rc4.y, rc4.z, rc4.w};
    int cc[4] = {cc4.x, cc4.y, cc4.z, cc4.w};
    float w[4] = {w4.x, w4.y, w4.z, w4.w};

    float dtr[4];
    float4 xd[4];
    #pragma unroll
    for (int k = 0; k < 4; k++) {
        dtr[k] = g_dis_t[rt[k]];
        xd[k]  = g_xd4[rc[k]];
    }
    #pragma unroll
    for (int k = 0; k < 4; k++) {
        atomicAdd(&g_sum_t[ct[k]], dtr[k]);
        float nw = xd[k].w * w[k];
        red_add_v4(&g_gc4[cc[k]], nw * xd[k].x, nw * xd[k].y, nw * xd[k].z, 0.f);
    }
}

// ---- k4: dest-side scaling + self-loops -> u; restore zeros for next call ----
__global__ void k_u() {
    int n = blockIdx.x * blockDim.x + threadIdx.x;
    if (n >= NT + NC) return;
    float4 u;
    if (n < NT) {
        float d = g_dis_t[n];
        u = make_float4(d * g_sum_t[n] + d * d, 1.f, 0.f, 0.f);
        g_dis_t[n] = 0.f;
        g_sum_t[n] = 0.f;
    } else {
        int c = n - NT;
        float4 gc = g_gc4[c];
        float4 xd = g_xd4[c];
        float d  = xd.w;
        float dd = d * d;
        u = make_float4(d * gc.x + dd * xd.x,
                        d * gc.y + dd * xd.y,
                        d * gc.z + dd * xd.z,
                        1.f);
        g_gc4[c] = make_float4(0.f, 0.f, 0.f, 0.f);
        g_deg_c[c] = 0.f;
    }
    g_u[n] = u;
}

// ---- k5: pair scoring, 2 pairs/thread ----
__global__ void __launch_bounds__(256) k_pair(const int* __restrict__ src,
                                              const int* __restrict__ dst,
                                              const float* __restrict__ bl,
                                              float* __restrict__ out) {
    __shared__ float M[36];
    if (threadIdx.x < 36) M[threadIdx.x] = g_M[threadIdx.x];
    __syncthreads();
    int t = blockIdx.x * blockDim.x + threadIdx.x;
    int base = t * 2;
    if (base >= NP) return;
    int2 s2 = *(const int2*)(src + base);
    int2 d2 = *(const int2*)(dst + base);
    float blv = bl[0];
    int ss[2] = {s2.x, s2.y};
    int dd[2] = {d2.x, d2.y};
    float4 usv[2], udv[2];
    #pragma unroll
    for (int k = 0; k < 2; k++) { usv[k] = g_u[ss[k]]; udv[k] = g_u[dd[k]]; }
    float res[2];
    #pragma unroll
    for (int k = 0; k < 2; k++) {
        float us[6] = {0.f, 0.f, 0.f, 0.f, 0.f, 0.f};
        float ud[6] = {0.f, 0.f, 0.f, 0.f, 0.f, 0.f};
        if (ss[k] < NT) { us[0] = usv[k].x; us[1] = usv[k].y; }
        else            { us[2] = usv[k].x; us[3] = usv[k].y; us[4] = usv[k].z; us[5] = usv[k].w; }
        if (dd[k] < NT) { ud[0] = udv[k].x; ud[1] = udv[k].y; }
        else            { ud[2] = udv[k].x; ud[3] = udv[k].y; ud[4] = udv[k].z; ud[5] = udv[k].w; }
        float acc = blv;
        #pragma unroll
        for (int i = 0; i < 6; i++) {
            float tt = 0.f;
            #pragma unroll
            for (int j = 0; j < 6; j++)
                tt += M[6 * i + j] * ud[j];
            acc += us[i] * tt;
        }
        res[k] = acc;
    }
    out[base] = res[0];
    if (base + 1 < NP) out[base + 1] = res[1];
}

extern "C" void kernel_launch(void* const* d_in, const int* in_sizes, int n_in,
                              void* d_out, int out_size) {
    const float* xcar = (const float*)d_in[0];
    const int*   eit  = (const int*)d_in[1];
    const int*   eic  = (const int*)d_in[2];
    const float* ew   = (const float*)d_in[3];
    const int*   src  = (const int*)d_in[4];
    const int*   dst  = (const int*)d_in[5];
    int w0 = (in_sizes[6] == 1) ? 7 : 6;
    const float* Wt = (const float*)d_in[w0 + 0];
    const float* bt = (const float*)d_in[w0 + 1];
    const float* Wc = (const float*)d_in[w0 + 2];
    const float* bc = (const float*)d_in[w0 + 3];
    const float* wl = (const float*)d_in[w0 + 4];
    const float* bl = (const float*)d_in[w0 + 5];
    float* out = (float*)d_out;

    const int TPB = 256;
    k_M<<<1, HD>>>(Wt, bt, Wc, bc, wl);
    k_deg<<<(NE / 4 + TPB - 1) / TPB, TPB>>>(eit, eic, ew);
    k_dis<<<(NC / 4 + TPB - 1) / TPB, TPB>>>(xcar);
    k_agg<<<(NE / 4 + TPB - 1) / TPB, TPB>>>(eit, eic, ew);
    k_u<<<(NT + NC + TPB - 1) / TPB, TPB>>>();
    k_pair<<<(NP / 2 + TPB - 1) / TPB, TPB>>>(src, dst, bl, out);
}

// round 8
// speedup vs baseline: 1.0475x; 1.0040x over previous
#include <cuda_runtime.h>

#define NT 100000
#define NC 100000
#define NE 1600000
#define NP 200000
#define HD 128

// ---- scratch (static __device__, zero at load; k_u restores zeros each call) ----
__device__ float  g_dis_t[NT];     // truck deg -> dis_t
__device__ float  g_sum_t[NT];     // unscaled truck sum
__device__ float  g_deg_c[NC];     // car weighted degree
__device__ float4 g_gc4[NC];       // unscaled car sum
__device__ float4 g_xd4[NC];       // packed (x0,x1,x2,dis_c)
__device__ float4 g_u[NT + NC];    // per-node compact coefficients
__device__ float  g_M[36];         // 6x6 quadratic-form matrix

__device__ __forceinline__ void red_add_v4(float4* addr, float a, float b, float c, float d) {
    asm volatile("red.global.add.v4.f32 [%0], {%1,%2,%3,%4};"
                 :: "l"(addr), "f"(a), "f"(b), "f"(c), "f"(d) : "memory");
}
__device__ __forceinline__ int4 ldcs_i4(const int* p) {
    return __ldcs((const int4*)p);
}
__device__ __forceinline__ float4 ldcs_f4(const float* p) {
    return __ldcs((const float4*)p);
}

// ---- kM: 6x6 quadratic form ----
__global__ void k_M(const float* __restrict__ Wt, const float* __restrict__ bt,
                    const float* __restrict__ Wc, const float* __restrict__ bc,
                    const float* __restrict__ wl) {
    __shared__ float B[6][HD];
    __shared__ float Bw[HD];
    int h = threadIdx.x;  // 128 threads
    B[0][h] = Wt[h];
    B[1][h] = bt[h];
    B[2][h] = Wc[h];
    B[3][h] = Wc[HD + h];
    B[4][h] = Wc[2 * HD + h];
    B[5][h] = bc[h];
    Bw[h] = wl[h];
    __syncthreads();
    int warp = h >> 5, lane = h & 31;
    for (int pi = warp; pi < 36; pi += 4) {
        int i = pi / 6, j = pi % 6;
        float s = 0.f;
        #pragma unroll
        for (int t = lane; t < HD; t += 32)
            s += B[i][t] * B[j][t] * Bw[t];
        #pragma unroll
        for (int o = 16; o > 0; o >>= 1)
            s += __shfl_xor_sync(0xffffffff, s, o);
        if (lane == 0) g_M[pi] = s;
    }
}

// ---- k1: degree accumulation, 4 edges/thread, streaming loads ----
__global__ void __launch_bounds__(256, 8) k_deg(const int* __restrict__ eit,
                                                const int* __restrict__ eic,
                                                const float* __restrict__ ew) {
    int t = blockIdx.x * blockDim.x + threadIdx.x;
    int base = t * 4;
    if (base >= NE) return;
    int4   ct4 = ldcs_i4(eit + NE + base);
    int4   cc4 = ldcs_i4(eic + NE + base);
    float4 w4  = ldcs_f4(ew + base);
    atomicAdd(&g_dis_t[ct4.x], 1.0f);
    atomicAdd(&g_dis_t[ct4.y], 1.0f);
    atomicAdd(&g_dis_t[ct4.z], 1.0f);
    atomicAdd(&g_dis_t[ct4.w], 1.0f);
    atomicAdd(&g_deg_c[cc4.x], w4.x);
    atomicAdd(&g_deg_c[cc4.y], w4.y);
    atomicAdd(&g_deg_c[cc4.z], w4.z);
    atomicAdd(&g_deg_c[cc4.w], w4.w);
}

// ---- k2: deg -> dis; pack (x0,x1,x2,dis_c); 4 nodes/thread ----
__global__ void __launch_bounds__(256) k_dis(const float* __restrict__ xcar) {
    int t = blockIdx.x * blockDim.x + threadIdx.x;
    int i = t * 4;
    if (i >= NC) return;
    float4 dt = *(float4*)&g_dis_t[i];
    float4 dc = *(float4*)&g_deg_c[i];
    float4 x0 = __ldcs((const float4*)(xcar + 3 * i));
    float4 x1 = __ldcs((const float4*)(xcar + 3 * i + 4));
    float4 x2 = __ldcs((const float4*)(xcar + 3 * i + 8));
    dt.x = rsqrtf(dt.x + 1.0f); dt.y = rsqrtf(dt.y + 1.0f);
    dt.z = rsqrtf(dt.z + 1.0f); dt.w = rsqrtf(dt.w + 1.0f);
    *(float4*)&g_dis_t[i] = dt;
    float d0 = rsqrtf(dc.x + 1.0f), d1 = rsqrtf(dc.y + 1.0f);
    float d2 = rsqrtf(dc.z + 1.0f), d3 = rsqrtf(dc.w + 1.0f);
    g_xd4[i + 0] = make_float4(x0.x, x0.y, x0.z, d0);
    g_xd4[i + 1] = make_float4(x0.w, x1.x, x1.y, d1);
    g_xd4[i + 2] = make_float4(x1.z, x1.w, x2.x, d2);
    g_xd4[i + 3] = make_float4(x2.y, x2.z, x2.w, d3);
}

// ---- k3: edge aggregation, 4 edges/thread, streaming edge loads + cached gathers ----
__global__ void __launch_bounds__(256, 6) k_agg(const int* __restrict__ eit,
                                                const int* __restrict__ eic,
                                                const float* __restrict__ ew) {
    int t = blockIdx.x * blockDim.x + threadIdx.x;
    int base = t * 4;
    if (base >= NE) return;
    int4   rt4 = ldcs_i4(eit + base);
    int4   ct4 = ldcs_i4(eit + NE + base);
    int4   rc4 = ldcs_i4(eic + base);
    int4   cc4 = ldcs_i4(eic + NE + base);
    float4 w4  = ldcs_f4(ew + base);

    int rt[4] = {rt4.x, rt4.y, rt4.z, rt4.w};
    int ct[4] = {ct4.x, ct4.y, ct4.z, ct4.w};
    int rc[4] = {rc4.x, rc4.y, rc4.z, rc4.w};
    int cc[4] = {cc4.x, cc4.y, cc4.z, cc4.w};
    float w[4] = {w4.x, w4.y, w4.z, w4.w};

    // gathers: default cache-all so they stay L1-resident
    float dtr[4];
    float4 xd[4];
    #pragma unroll
    for (int k = 0; k < 4; k++) {
        dtr[k] = g_dis_t[rt[k]];
        xd[k]  = g_xd4[rc[k]];
    }
    #pragma unroll
    for (int k = 0; k < 4; k++) {
        atomicAdd(&g_sum_t[ct[k]], dtr[k]);
        float nw = xd[k].w * w[k];
        red_add_v4(&g_gc4[cc[k]], nw * xd[k].x, nw * xd[k].y, nw * xd[k].z, 0.f);
    }
}

// ---- k4: dest-side scaling + self-loops -> u; restore zeros for next call ----
__global__ void k_u() {
    int n = blockIdx.x * blockDim.x + threadIdx.x;
    if (n >= NT + NC) return;
    float4 u;
    if (n < NT) {
        float d = g_dis_t[n];
        u = make_float4(d * g_sum_t[n] + d * d, 1.f, 0.f, 0.f);
        g_dis_t[n] = 0.f;
        g_sum_t[n] = 0.f;
    } else {
        int c = n - NT;
        float4 gc = g_gc4[c];
        float4 xd = g_xd4[c];
        float d  = xd.w;
        float dd = d * d;
        u = make_float4(d * gc.x + dd * xd.x,
                        d * gc.y + dd * xd.y,
                        d * gc.z + dd * xd.z,
                        1.f);
        g_gc4[c] = make_float4(0.f, 0.f, 0.f, 0.f);
        g_deg_c[c] = 0.f;
    }
    g_u[n] = u;
}

// ---- k5: pair scoring, 2 pairs/thread, streaming index loads ----
__global__ void __launch_bounds__(256) k_pair(const int* __restrict__ src,
                                              const int* __restrict__ dst,
                                              const float* __restrict__ bl,
                                              float* __restrict__ out) {
    __shared__ float M[36];
    if (threadIdx.x < 36) M[threadIdx.x] = g_M[threadIdx.x];
    __syncthreads();
    int t = blockIdx.x * blockDim.x + threadIdx.x;
    int base = t * 2;
    if (base >= NP) return;
    int2 s2 = __ldcs((const int2*)(src + base));
    int2 d2 = __ldcs((const int2*)(dst + base));
    float blv = bl[0];
    int ss[2] = {s2.x, s2.y};
    int dd[2] = {d2.x, d2.y};
    float4 usv[2], udv[2];
    #pragma unroll
    for (int k = 0; k < 2; k++) { usv[k] = g_u[ss[k]]; udv[k] = g_u[dd[k]]; }
    float res[2];
    #pragma unroll
    for (int k = 0; k < 2; k++) {
        float us[6] = {0.f, 0.f, 0.f, 0.f, 0.f, 0.f};
        float ud[6] = {0.f, 0.f, 0.f, 0.f, 0.f, 0.f};
        if (ss[k] < NT) { us[0] = usv[k].x; us[1] = usv[k].y; }
        else            { us[2] = usv[k].x; us[3] = usv[k].y; us[4] = usv[k].z; us[5] = usv[k].w; }
        if (dd[k] < NT) { ud[0] = udv[k].x; ud[1] = udv[k].y; }
        else            { ud[2] = udv[k].x; ud[3] = udv[k].y; ud[4] = udv[k].z; ud[5] = udv[k].w; }
        float acc = blv;
        #pragma unroll
        for (int i = 0; i < 6; i++) {
            float tt = 0.f;
            #pragma unroll
            for (int j = 0; j < 6; j++)
                tt += M[6 * i + j] * ud[j];
            acc += us[i] * tt;
        }
        res[k] = acc;
    }
    out[base] = res[0];
    if (base + 1 < NP) out[base + 1] = res[1];
}

extern "C" void kernel_launch(void* const* d_in, const int* in_sizes, int n_in,
                              void* d_out, int out_size) {
    const float* xcar = (const float*)d_in[0];
    const int*   eit  = (const int*)d_in[1];
    const int*   eic  = (const int*)d_in[2];
    const float* ew   = (const float*)d_in[3];
    const int*   src  = (const int*)d_in[4];
    const int*   dst  = (const int*)d_in[5];
    int w0 = (in_sizes[6] == 1) ? 7 : 6;
    const float* Wt = (const float*)d_in[w0 + 0];
    const float* bt = (const float*)d_in[w0 + 1];
    const float* Wc = (const float*)d_in[w0 + 2];
    const float* bc = (const float*)d_in[w0 + 3];
    const float* wl = (const float*)d_in[w0 + 4];
    const float* bl = (const float*)d_in[w0 + 5];
    float* out = (float*)d_out;

    const int TPB = 256;
    k_M<<<1, HD>>>(Wt, bt, Wc, bc, wl);
    k_deg<<<(NE / 4 + TPB - 1) / TPB, TPB>>>(eit, eic, ew);
    k_dis<<<(NC / 4 + TPB - 1) / TPB, TPB>>>(xcar);
    k_agg<<<(NE / 4 + TPB - 1) / TPB, TPB>>>(eit, eic, ew);
    k_u<<<(NT + NC + TPB - 1) / TPB, TPB>>>();
    k_pair<<<(NP / 2 + TPB - 1) / TPB, TPB>>>(src, dst, bl, out);
}

// round 9
// speedup vs baseline: 1.0969x; 1.0471x over previous
#include <cuda_runtime.h>

#define NT 100000
#define NC 100000
#define NE 1600000
#define NP 200000
#define HD 128

// ---- scratch (static __device__, zero at load; k_u* restore zeros each call) ----
__device__ float  g_dis_t[NT];     // truck deg -> dis_t
__device__ float  g_sum_t[NT];     // unscaled truck sum
__device__ float  g_deg_c[NC];     // car weighted degree
__device__ float4 g_gc4[NC];       // unscaled car sum
__device__ float4 g_xd4[NC];       // packed (x0,x1,x2,dis_c)
__device__ float4 g_u[NT + NC];    // per-node compact coefficients
__device__ float  g_M[36];         // 6x6 quadratic-form matrix

__device__ __forceinline__ void red_add_v4(float4* addr, float a, float b, float c, float d) {
    asm volatile("red.global.add.v4.f32 [%0], {%1,%2,%3,%4};"
                 :: "l"(addr), "f"(a), "f"(b), "f"(c), "f"(d) : "memory");
}

// ================= truck chain =================
__global__ void __launch_bounds__(256, 8) k_deg_t(const int* __restrict__ eit) {
    int t = blockIdx.x * blockDim.x + threadIdx.x;
    int base = t * 4;
    if (base >= NE) return;
    int4 ct4 = __ldcs((const int4*)(eit + NE + base));
    atomicAdd(&g_dis_t[ct4.x], 1.0f);
    atomicAdd(&g_dis_t[ct4.y], 1.0f);
    atomicAdd(&g_dis_t[ct4.z], 1.0f);
    atomicAdd(&g_dis_t[ct4.w], 1.0f);
}

__global__ void __launch_bounds__(256) k_dis_t() {
    int t = blockIdx.x * blockDim.x + threadIdx.x;
    int i = t * 4;
    if (i >= NT) return;
    float4 dt = *(float4*)&g_dis_t[i];
    dt.x = rsqrtf(dt.x + 1.0f); dt.y = rsqrtf(dt.y + 1.0f);
    dt.z = rsqrtf(dt.z + 1.0f); dt.w = rsqrtf(dt.w + 1.0f);
    *(float4*)&g_dis_t[i] = dt;
}

__global__ void __launch_bounds__(256, 6) k_agg_t(const int* __restrict__ eit) {
    int t = blockIdx.x * blockDim.x + threadIdx.x;
    int base = t * 4;
    if (base >= NE) return;
    int4 rt4 = __ldcs((const int4*)(eit + base));
    int4 ct4 = __ldcs((const int4*)(eit + NE + base));
    int rt[4] = {rt4.x, rt4.y, rt4.z, rt4.w};
    int ct[4] = {ct4.x, ct4.y, ct4.z, ct4.w};
    float dtr[4];
    #pragma unroll
    for (int k = 0; k < 4; k++) dtr[k] = g_dis_t[rt[k]];
    #pragma unroll
    for (int k = 0; k < 4; k++) atomicAdd(&g_sum_t[ct[k]], dtr[k]);
}

__global__ void __launch_bounds__(256) k_u_t() {
    int n = blockIdx.x * blockDim.x + threadIdx.x;
    if (n >= NT) return;
    float d = g_dis_t[n];
    g_u[n] = make_float4(d * g_sum_t[n] + d * d, 1.f, 0.f, 0.f);
    g_dis_t[n] = 0.f;
    g_sum_t[n] = 0.f;
}

// ================= car chain =================
__global__ void __launch_bounds__(256, 8) k_deg_c(const int* __restrict__ eic,
                                                  const float* __restrict__ ew) {
    int t = blockIdx.x * blockDim.x + threadIdx.x;
    int base = t * 4;
    if (base >= NE) return;
    int4   cc4 = __ldcs((const int4*)(eic + NE + base));
    float4 w4  = __ldcs((const float4*)(ew + base));
    atomicAdd(&g_deg_c[cc4.x], w4.x);
    atomicAdd(&g_deg_c[cc4.y], w4.y);
    atomicAdd(&g_deg_c[cc4.z], w4.z);
    atomicAdd(&g_deg_c[cc4.w], w4.w);
}

__global__ void __launch_bounds__(256) k_dis_c(const float* __restrict__ xcar) {
    int t = blockIdx.x * blockDim.x + threadIdx.x;
    int i = t * 4;
    if (i >= NC) return;
    float4 dc = *(float4*)&g_deg_c[i];
    float4 x0 = __ldcs((const float4*)(xcar + 3 * i));
    float4 x1 = __ldcs((const float4*)(xcar + 3 * i + 4));
    float4 x2 = __ldcs((const float4*)(xcar + 3 * i + 8));
    float d0 = rsqrtf(dc.x + 1.0f), d1 = rsqrtf(dc.y + 1.0f);
    float d2 = rsqrtf(dc.z + 1.0f), d3 = rsqrtf(dc.w + 1.0f);
    g_xd4[i + 0] = make_float4(x0.x, x0.y, x0.z, d0);
    g_xd4[i + 1] = make_float4(x0.w, x1.x, x1.y, d1);
    g_xd4[i + 2] = make_float4(x1.z, x1.w, x2.x, d2);
    g_xd4[i + 3] = make_float4(x2.y, x2.z, x2.w, d3);
}

__global__ void __launch_bounds__(256, 6) k_agg_c(const int* __restrict__ eic,
                                                  const float* __restrict__ ew) {
    int t = blockIdx.x * blockDim.x + threadIdx.x;
    int base = t * 4;
    if (base >= NE) return;
    int4   rc4 = __ldcs((const int4*)(eic + base));
    int4   cc4 = __ldcs((const int4*)(eic + NE + base));
    float4 w4  = __ldcs((const float4*)(ew + base));
    int rc[4] = {rc4.x, rc4.y, rc4.z, rc4.w};
    int cc[4] = {cc4.x, cc4.y, cc4.z, cc4.w};
    float w[4] = {w4.x, w4.y, w4.z, w4.w};
    float4 xd[4];
    #pragma unroll
    for (int k = 0; k < 4; k++) xd[k] = g_xd4[rc[k]];
    #pragma unroll
    for (int k = 0; k < 4; k++) {
        float nw = xd[k].w * w[k];
        red_add_v4(&g_gc4[cc[k]], nw * xd[k].x, nw * xd[k].y, nw * xd[k].z, 0.f);
    }
}

__global__ void __launch_bounds__(256) k_u_c() {
    int c = blockIdx.x * blockDim.x + threadIdx.x;
    if (c >= NC) return;
    float4 gc = g_gc4[c];
    float4 xd = g_xd4[c];
    float d  = xd.w;
    float dd = d * d;
    g_u[NT + c] = make_float4(d * gc.x + dd * xd.x,
                              d * gc.y + dd * xd.y,
                              d * gc.z + dd * xd.z,
                              1.f);
    g_gc4[c] = make_float4(0.f, 0.f, 0.f, 0.f);
    g_deg_c[c] = 0.f;
}

// ================= weights / scoring =================
__global__ void k_M(const float* __restrict__ Wt, const float* __restrict__ bt,
                    const float* __restrict__ Wc, const float* __restrict__ bc,
                    const float* __restrict__ wl) {
    __shared__ float B[6][HD];
    __shared__ float Bw[HD];
    int h = threadIdx.x;  // 128 threads
    B[0][h] = Wt[h];
    B[1][h] = bt[h];
    B[2][h] = Wc[h];
    B[3][h] = Wc[HD + h];
    B[4][h] = Wc[2 * HD + h];
    B[5][h] = bc[h];
    Bw[h] = wl[h];
    __syncthreads();
    int warp = h >> 5, lane = h & 31;
    for (int pi = warp; pi < 36; pi += 4) {
        int i = pi / 6, j = pi % 6;
        float s = 0.f;
        #pragma unroll
        for (int t = lane; t < HD; t += 32)
            s += B[i][t] * B[j][t] * Bw[t];
        #pragma unroll
        for (int o = 16; o > 0; o >>= 1)
            s += __shfl_xor_sync(0xffffffff, s, o);
        if (lane == 0) g_M[pi] = s;
    }
}

__global__ void __launch_bounds__(256) k_pair(const int* __restrict__ src,
                                              const int* __restrict__ dst,
                                              const float* __restrict__ bl,
                                              float* __restrict__ out) {
    __shared__ float M[36];
    if (threadIdx.x < 36) M[threadIdx.x] = g_M[threadIdx.x];
    __syncthreads();
    int t = blockIdx.x * blockDim.x + threadIdx.x;
    int base = t * 2;
    if (base >= NP) return;
    int2 s2 = __ldcs((const int2*)(src + base));
    int2 d2 = __ldcs((const int2*)(dst + base));
    float blv = bl[0];
    int ss[2] = {s2.x, s2.y};
    int dd[2] = {d2.x, d2.y};
    float4 usv[2], udv[2];
    #pragma unroll
    for (int k = 0; k < 2; k++) { usv[k] = g_u[ss[k]]; udv[k] = g_u[dd[k]]; }
    float res[2];
    #pragma unroll
    for (int k = 0; k < 2; k++) {
        float us[6] = {0.f, 0.f, 0.f, 0.f, 0.f, 0.f};
        float ud[6] = {0.f, 0.f, 0.f, 0.f, 0.f, 0.f};
        if (ss[k] < NT) { us[0] = usv[k].x; us[1] = usv[k].y; }
        else            { us[2] = usv[k].x; us[3] = usv[k].y; us[4] = usv[k].z; us[5] = usv[k].w; }
        if (dd[k] < NT) { ud[0] = udv[k].x; ud[1] = udv[k].y; }
        else            { ud[2] = udv[k].x; ud[3] = udv[k].y; ud[4] = udv[k].z; ud[5] = udv[k].w; }
        float acc = blv;
        #pragma unroll
        for (int i = 0; i < 6; i++) {
            float tt = 0.f;
            #pragma unroll
            for (int j = 0; j < 6; j++)
                tt += M[6 * i + j] * ud[j];
            acc += us[i] * tt;
        }
        res[k] = acc;
    }
    out[base] = res[0];
    if (base + 1 < NP) out[base + 1] = res[1];
}

extern "C" void kernel_launch(void* const* d_in, const int* in_sizes, int n_in,
                              void* d_out, int out_size) {
    const float* xcar = (const float*)d_in[0];
    const int*   eit  = (const int*)d_in[1];
    const int*   eic  = (const int*)d_in[2];
    const float* ew   = (const float*)d_in[3];
    const int*   src  = (const int*)d_in[4];
    const int*   dst  = (const int*)d_in[5];
    int w0 = (in_sizes[6] == 1) ? 7 : 6;
    const float* Wt = (const float*)d_in[w0 + 0];
    const float* bt = (const float*)d_in[w0 + 1];
    const float* Wc = (const float*)d_in[w0 + 2];
    const float* bc = (const float*)d_in[w0 + 3];
    const float* wl = (const float*)d_in[w0 + 4];
    const float* bl = (const float*)d_in[w0 + 5];
    float* out = (float*)d_out;

    // one-time infra (no device memory): side stream + fork/join events.
    static cudaStream_t s2 = 0;
    static cudaEvent_t ev_fork = 0, ev_join = 0;
    if (s2 == 0) {
        cudaStreamCreateWithFlags(&s2, cudaStreamNonBlocking);
        cudaEventCreateWithFlags(&ev_fork, cudaEventDisableTiming);
        cudaEventCreateWithFlags(&ev_join, cudaEventDisableTiming);
    }

    const int TPB = 256;
    const int GE = (NE / 4 + TPB - 1) / TPB;

    // fork: car chain on s2, truck chain on default stream
    cudaEventRecord(ev_fork, 0);
    cudaStreamWaitEvent(s2, ev_fork, 0);

    // car chain (+ k_M) on s2
    k_M<<<1, HD, 0, s2>>>(Wt, bt, Wc, bc, wl);
    k_deg_c<<<GE, TPB, 0, s2>>>(eic, ew);
    k_dis_c<<<(NC / 4 + TPB - 1) / TPB, TPB, 0, s2>>>(xcar);
    k_agg_c<<<GE, TPB, 0, s2>>>(eic, ew);
    k_u_c<<<(NC + TPB - 1) / TPB, TPB, 0, s2>>>();
    cudaEventRecord(ev_join, s2);

    // truck chain on default stream
    k_deg_t<<<GE, TPB>>>(eit);
    k_dis_t<<<(NT / 4 + TPB - 1) / TPB, TPB>>>();
    k_agg_t<<<GE, TPB>>>(eit);
    k_u_t<<<(NT + TPB - 1) / TPB, TPB>>>();

    // join + score
    cudaStreamWaitEvent(0, ev_join, 0);
    k_pair<<<(NP / 2 + TPB - 1) / TPB, TPB>>>(src, dst, bl, out);
}